// round 6
// baseline (speedup 1.0000x reference)
#include <cuda_runtime.h>

// Problem constants (fixed by the dataset)
#define NN 50000      // nodes
#define HH 5000       // hyperedges
#define EE 400000     // incidence entries
#define BB 2          // batch
#define CC 64         // channels
#define RR (NN*BB)    // 100000 "rows" (n,b) pairs, r = 2*n + b
#define NBLK 49       // ceil(NN/1024) for the scan

// ---------------------------------------------------------------------------
// Scratch: __device__ globals (no runtime allocation allowed)
// ---------------------------------------------------------------------------
__device__ __align__(16) float g_xw[RR * CC];     // projected features [r][c] (25.6 MB)
__device__ __align__(16) float g_d1[RR];          // dot(xw, att[:C])  per (n,b)
__device__ __align__(16) float g_d2[RR];          // dot(xw, att[C:])  per (n,b)
__device__ int   g_Dn[NN];                        // node degree
__device__ int   g_De[HH];                        // hyperedge degree
__device__ int   g_hstart[HH];                    // start offset per hyperedge (hedge sorted)
__device__ int   g_nstart[NN];                    // start offset per node (after scan)
__device__ int   g_cursor[NN];                    // scatter cursors
__device__ int   g_perm[EE];                      // node-sorted permutation of incidences
__device__ __align__(16) float g_aedge[HH * 2];   // per-hyperedge attention scalar
__device__ __align__(16) float g_alpha[EE * 2];   // normalized attention [e][b]
__device__ __align__(16) float g_m[HH * 128];     // hyperedge messages [h][b*64+c] (2.56 MB)
__device__ int   g_bsum[64];                      // scan block sums

// ---------------------------------------------------------------------------
// K0: zero counters
// ---------------------------------------------------------------------------
__global__ void k_zero() {
    int i = blockIdx.x * blockDim.x + threadIdx.x;
    if (i < NN) { g_Dn[i] = 0; g_cursor[i] = 0; }
    if (i < HH) { g_De[i] = 0; }
}

// ---------------------------------------------------------------------------
// K1: GEMM  xw[r][d] = sum_c x[b][n][c] * W[c][d],  r = 2n+b
//     + per-row dots d1[r] = xw[r]·att1, d2[r] = xw[r]·att2
// Block: 256 threads handle 16 rows x 16 thread-groups of 4 channels.
// ---------------------------------------------------------------------------
__global__ void k_gemm(const float* __restrict__ x,
                       const float* __restrict__ W,
                       const float* __restrict__ att) {
    __shared__ float Ws[64 * 64];
    __shared__ float xs[16 * 68];   // stride 68 floats: 16B aligned, conflict-free

    int tid = threadIdx.x;
    // load weight (4096 floats = 1024 float4)
    for (int i = tid; i < 1024; i += 256)
        ((float4*)Ws)[i] = ((const float4*)W)[i];

    int rowblock = blockIdx.x * 16;
    {
        int rl = tid >> 4;          // 0..15 local row
        int cq = tid & 15;          // float4 index within row
        int r  = rowblock + rl;
        float4 v = make_float4(0.f, 0.f, 0.f, 0.f);
        if (r < RR) {
            int n = r >> 1, b = r & 1;
            v = ((const float4*)(x + (size_t)b * NN * 64 + (size_t)n * 64))[cq];
        }
        ((float4*)(xs + rl * 68))[cq] = v;
    }
    __syncthreads();

    int rl = tid >> 4;
    int r  = rowblock + rl;
    int d0 = (tid & 15) * 4;
    float4 acc = make_float4(0.f, 0.f, 0.f, 0.f);
#pragma unroll
    for (int c = 0; c < 64; c++) {
        float  xv = xs[rl * 68 + c];
        float4 w  = *(const float4*)(Ws + c * 64 + d0);
        acc.x += xv * w.x; acc.y += xv * w.y;
        acc.z += xv * w.z; acc.w += xv * w.w;
    }
    if (r < RR) {
        *(float4*)(g_xw + (size_t)r * 64 + d0) = acc;
        float p1 = acc.x * __ldg(att + d0)      + acc.y * __ldg(att + d0 + 1)
                 + acc.z * __ldg(att + d0 + 2)  + acc.w * __ldg(att + d0 + 3);
        float p2 = acc.x * __ldg(att + 64 + d0)     + acc.y * __ldg(att + 64 + d0 + 1)
                 + acc.z * __ldg(att + 64 + d0 + 2) + acc.w * __ldg(att + 64 + d0 + 3);
        // reduce across the 16 lanes owning this row (xor<16 stays in-half)
#pragma unroll
        for (int off = 8; off >= 1; off >>= 1) {
            p1 += __shfl_xor_sync(0xffffffffu, p1, off);
            p2 += __shfl_xor_sync(0xffffffffu, p2, off);
        }
        if ((tid & 15) == 0) { g_d1[r] = p1; g_d2[r] = p2; }
    }
}

// ---------------------------------------------------------------------------
// K2: degrees + hyperedge segment starts (hedge_idx is sorted)
// ---------------------------------------------------------------------------
__global__ void k_deg(const int* __restrict__ node_idx,
                      const int* __restrict__ hedge_idx) {
    int e = blockIdx.x * blockDim.x + threadIdx.x;
    if (e >= EE) return;
    atomicAdd(&g_Dn[node_idx[e]], 1);
    int h = hedge_idx[e];
    atomicAdd(&g_De[h], 1);
    if (e == 0 || hedge_idx[e - 1] != h) g_hstart[h] = e;
}

// ---------------------------------------------------------------------------
// K3a/b/c: exclusive scan of g_Dn -> g_nstart (two-level, 1024-wide blocks)
// ---------------------------------------------------------------------------
__global__ void k_scan1() {
    int i    = blockIdx.x * 1024 + threadIdx.x;
    int lane = threadIdx.x & 31, wid = threadIdx.x >> 5;
    int v = (i < NN) ? g_Dn[i] : 0;
    int x = v;
#pragma unroll
    for (int off = 1; off < 32; off <<= 1) {
        int y = __shfl_up_sync(0xffffffffu, x, off);
        if (lane >= off) x += y;
    }
    __shared__ int ws[32];
    if (lane == 31) ws[wid] = x;
    __syncthreads();
    if (wid == 0) {
        int s = ws[lane];
#pragma unroll
        for (int off = 1; off < 32; off <<= 1) {
            int y = __shfl_up_sync(0xffffffffu, s, off);
            if (lane >= off) s += y;
        }
        ws[lane] = s;
    }
    __syncthreads();
    int excl = x - v + ((wid > 0) ? ws[wid - 1] : 0);
    if (i < NN) g_nstart[i] = excl;
    if (threadIdx.x == 1023) g_bsum[blockIdx.x] = excl + v;
}

__global__ void k_scan2() {
    if (threadIdx.x == 0) {
        int s = 0;
        for (int k = 0; k < NBLK; k++) { int t = g_bsum[k]; g_bsum[k] = s; s += t; }
    }
}

__global__ void k_scan3() {
    int i = blockIdx.x * 1024 + threadIdx.x;
    if (i < NN) g_nstart[i] += g_bsum[blockIdx.x];
}

// ---------------------------------------------------------------------------
// K4: per-hyperedge attention scalar a_edge[h][b] = sum_{e in h} d2[2*node_e + b]
// (eliminates the [H,B,C] edge_sums tensor entirely)
// ---------------------------------------------------------------------------
__global__ void k_aedge(const int* __restrict__ node_idx) {
    int h = blockIdx.x;
    int cnt = g_De[h];
    if (cnt == 0) return;
    int start = g_hstart[h];
    int t = threadIdx.x;            // 128 threads = 4 warps
    float s0 = 0.f, s1 = 0.f;
    for (int i = t; i < cnt; i += 128) {
        int n = node_idx[start + i];
        float2 d = *(const float2*)(g_d2 + 2 * n);
        s0 += d.x; s1 += d.y;
    }
#pragma unroll
    for (int off = 16; off >= 1; off >>= 1) {
        s0 += __shfl_xor_sync(0xffffffffu, s0, off);
        s1 += __shfl_xor_sync(0xffffffffu, s1, off);
    }
    __shared__ float r0[4], r1[4];
    int lane = t & 31, wid = t >> 5;
    if (lane == 0) { r0[wid] = s0; r1[wid] = s1; }
    __syncthreads();
    if (t == 0) {
        float a0 = r0[0] + r0[1] + r0[2] + r0[3];
        float a1 = r1[0] + r1[1] + r1[2] + r1[3];
        g_aedge[2 * h]     = a0;
        g_aedge[2 * h + 1] = a1;
    }
}

// ---------------------------------------------------------------------------
// K5: counting-sort scatter: perm lists incidences grouped by node
// ---------------------------------------------------------------------------
__global__ void k_scatter(const int* __restrict__ node_idx) {
    int e = blockIdx.x * blockDim.x + threadIdx.x;
    if (e >= EE) return;
    int n = node_idx[e];
    int pos = g_nstart[n] + atomicAdd(&g_cursor[n], 1);
    g_perm[pos] = e;
}

// ---------------------------------------------------------------------------
// K6: segment softmax over node segments (warp per node)
// alpha_raw[e][b] = leakyrelu(d1[2n+b] + a_edge[2h+b], 0.2)
// ---------------------------------------------------------------------------
__global__ void k_softmax(const int* __restrict__ hedge_idx) {
    int gw   = (blockIdx.x * blockDim.x + threadIdx.x) >> 5;
    int lane = threadIdx.x & 31;
    if (gw >= NN) return;
    int n = gw, deg = g_Dn[n];
    if (deg == 0) return;
    int start = g_nstart[n];
    float base0 = g_d1[2 * n], base1 = g_d1[2 * n + 1];

    if (deg <= 32) {
        int e = 0;
        float v0 = -1e30f, v1 = -1e30f;
        if (lane < deg) {
            e = g_perm[start + lane];
            int h = hedge_idx[e];
            v0 = base0 + g_aedge[2 * h];
            v1 = base1 + g_aedge[2 * h + 1];
            v0 = (v0 >= 0.f) ? v0 : 0.2f * v0;
            v1 = (v1 >= 0.f) ? v1 : 0.2f * v1;
        }
        float m0 = v0, m1 = v1;
#pragma unroll
        for (int off = 16; off >= 1; off >>= 1) {
            m0 = fmaxf(m0, __shfl_xor_sync(0xffffffffu, m0, off));
            m1 = fmaxf(m1, __shfl_xor_sync(0xffffffffu, m1, off));
        }
        float e0 = (lane < deg) ? __expf(v0 - m0) : 0.f;
        float e1 = (lane < deg) ? __expf(v1 - m1) : 0.f;
        float s0 = e0, s1 = e1;
#pragma unroll
        for (int off = 16; off >= 1; off >>= 1) {
            s0 += __shfl_xor_sync(0xffffffffu, s0, off);
            s1 += __shfl_xor_sync(0xffffffffu, s1, off);
        }
        if (lane < deg) {
            g_alpha[2 * e]     = e0 / s0;
            g_alpha[2 * e + 1] = e1 / s1;
        }
    } else {
        // 3-pass recompute path for rare high-degree nodes
        float m0 = -1e30f, m1 = -1e30f;
        for (int j = lane; j < deg; j += 32) {
            int e = g_perm[start + j]; int h = hedge_idx[e];
            float v0 = base0 + g_aedge[2 * h];
            float v1 = base1 + g_aedge[2 * h + 1];
            v0 = (v0 >= 0.f) ? v0 : 0.2f * v0;
            v1 = (v1 >= 0.f) ? v1 : 0.2f * v1;
            m0 = fmaxf(m0, v0); m1 = fmaxf(m1, v1);
        }
#pragma unroll
        for (int off = 16; off >= 1; off >>= 1) {
            m0 = fmaxf(m0, __shfl_xor_sync(0xffffffffu, m0, off));
            m1 = fmaxf(m1, __shfl_xor_sync(0xffffffffu, m1, off));
        }
        float s0 = 0.f, s1 = 0.f;
        for (int j = lane; j < deg; j += 32) {
            int e = g_perm[start + j]; int h = hedge_idx[e];
            float v0 = base0 + g_aedge[2 * h];
            float v1 = base1 + g_aedge[2 * h + 1];
            v0 = (v0 >= 0.f) ? v0 : 0.2f * v0;
            v1 = (v1 >= 0.f) ? v1 : 0.2f * v1;
            s0 += __expf(v0 - m0); s1 += __expf(v1 - m1);
        }
#pragma unroll
        for (int off = 16; off >= 1; off >>= 1) {
            s0 += __shfl_xor_sync(0xffffffffu, s0, off);
            s1 += __shfl_xor_sync(0xffffffffu, s1, off);
        }
        for (int j = lane; j < deg; j += 32) {
            int e = g_perm[start + j]; int h = hedge_idx[e];
            float v0 = base0 + g_aedge[2 * h];
            float v1 = base1 + g_aedge[2 * h + 1];
            v0 = (v0 >= 0.f) ? v0 : 0.2f * v0;
            v1 = (v1 >= 0.f) ? v1 : 0.2f * v1;
            g_alpha[2 * e]     = __expf(v0 - m0) / s0;
            g_alpha[2 * e + 1] = __expf(v1 - m1) / s1;
        }
    }
}

// ---------------------------------------------------------------------------
// K7: pass1 nodes -> hyperedges: m[h][b*64+c] = (1/De) * sum alpha[e][b]*xw[node]
// block per hyperedge (hedge-sorted -> contiguous segment, no atomics)
// ---------------------------------------------------------------------------
__global__ void k_pass1(const int* __restrict__ node_idx) {
    int h = blockIdx.x;
    int cnt = g_De[h];
    if (cnt == 0) return;
    int start = g_hstart[h];
    int t = threadIdx.x;            // 128 = B*C, thread owns (b,c)
    int b = t >> 6;
    __shared__ int   sn[128];
    __shared__ float sa0[128], sa1[128];
    float acc = 0.f;
    for (int base = 0; base < cnt; base += 128) {
        int mlen = min(128, cnt - base);
        if (t < mlen) {
            int e = start + base + t;
            sn[t] = node_idx[e];
            float2 a = *(const float2*)(g_alpha + 2 * e);
            sa0[t] = a.x; sa1[t] = a.y;
        }
        __syncthreads();
        const float* sa = b ? sa1 : sa0;
#pragma unroll 4
        for (int i = 0; i < mlen; i++) {
            acc += sa[i] * g_xw[(size_t)sn[i] * 128 + t];
        }
        __syncthreads();
    }
    g_m[(size_t)h * 128 + t] = acc / (float)cnt;
}

// ---------------------------------------------------------------------------
// K8: pass2 hyperedges -> nodes: out[b][n][c] = Dn[n] * sum alpha[e][b]*m[h_e]
// warp per node on the node-sorted permutation (no atomics, m is L2-resident)
// ---------------------------------------------------------------------------
__global__ void k_pass2(const int* __restrict__ hedge_idx,
                        float* __restrict__ out) {
    int gw   = (blockIdx.x * blockDim.x + threadIdx.x) >> 5;
    int lane = threadIdx.x & 31;
    if (gw >= NN) return;
    int n = gw, deg = g_Dn[n];
    int start = g_nstart[n];
    float4 acc = make_float4(0.f, 0.f, 0.f, 0.f);

    for (int base = 0; base < deg; base += 32) {
        int cnt = min(32, deg - base);
        int h = 0; float2 a2 = make_float2(0.f, 0.f);
        if (lane < cnt) {
            int e = g_perm[start + base + lane];
            h  = hedge_idx[e];
            a2 = *(const float2*)(g_alpha + 2 * e);
        }
        for (int i = 0; i < cnt; i++) {
            int   hh = __shfl_sync(0xffffffffu, h,    i);
            float a0 = __shfl_sync(0xffffffffu, a2.x, i);
            float a1 = __shfl_sync(0xffffffffu, a2.y, i);
            float a  = (lane < 16) ? a0 : a1;
            float4 mv = *(const float4*)(g_m + (size_t)hh * 128 + lane * 4);
            acc.x += a * mv.x; acc.y += a * mv.y;
            acc.z += a * mv.z; acc.w += a * mv.w;
        }
    }
    float dn = (float)deg;          // Dn multiplies (NOT inverted in source)
    int b  = lane >> 4;
    int c0 = (lane & 15) * 4;
    float4 o = make_float4(dn * acc.x, dn * acc.y, dn * acc.z, dn * acc.w);
    *(float4*)(out + (size_t)b * NN * 64 + (size_t)n * 64 + c0) = o;
}

// ---------------------------------------------------------------------------
// Launch
// ---------------------------------------------------------------------------
extern "C" void kernel_launch(void* const* d_in, const int* in_sizes, int n_in,
                              void* d_out, int out_size) {
    const float* x         = (const float*)d_in[0];   // [B,N,C]
    const float* weight    = (const float*)d_in[1];   // [C,C]
    const float* att       = (const float*)d_in[2];   // [2C]
    const int*   node_idx  = (const int*)d_in[3];     // [E]
    const int*   hedge_idx = (const int*)d_in[4];     // [E] sorted
    float*       out       = (float*)d_out;           // [B,N,C]

    k_zero<<<(NN + 255) / 256, 256>>>();
    k_gemm<<<RR / 16, 256>>>(x, weight, att);
    k_deg<<<(EE + 255) / 256, 256>>>(node_idx, hedge_idx);
    k_scan1<<<NBLK, 1024>>>();
    k_scan2<<<1, 32>>>();
    k_scan3<<<NBLK, 1024>>>();
    k_aedge<<<HH, 128>>>(node_idx);
    k_scatter<<<(EE + 255) / 256, 256>>>(node_idx);
    k_softmax<<<(NN * 32 + 255) / 256, 256>>>(hedge_idx);
    k_pass1<<<HH, 128>>>(node_idx);
    k_pass2<<<(NN * 32 + 255) / 256, 256>>>(hedge_idx, out);
}

// round 7
// speedup vs baseline: 1.0036x; 1.0036x over previous
#include <cuda_runtime.h>

// Problem constants (fixed by the dataset)
#define NN 50000      // nodes
#define HH 5000       // hyperedges
#define EE 400000     // incidence entries
#define BB 2          // batch
#define CC 64         // channels
#define RR (NN*BB)    // 100000 "rows" (n,b) pairs, r = 2*n + b
#define NBLK 49       // ceil(NN/1024) for the scan

// ---------------------------------------------------------------------------
// Scratch: __device__ globals (no runtime allocation allowed)
// ---------------------------------------------------------------------------
__device__ __align__(16) float g_xw[RR * CC];     // projected features [r][c] (25.6 MB)
__device__ __align__(16) float g_d1[RR];          // dot(xw, att[:C])  per (n,b)
__device__ __align__(16) float g_d2[RR];          // dot(xw, att[C:])  per (n,b)
__device__ int   g_Dn[NN];                        // node degree
__device__ int   g_De[HH];                        // hyperedge degree
__device__ int   g_hstart[HH];                    // start offset per hyperedge (hedge sorted)
__device__ int   g_nstart[NN];                    // start offset per node (after scan)
__device__ int   g_cursor[NN];                    // scatter cursors
__device__ int   g_perm[EE];                      // node-sorted permutation of incidences
__device__ __align__(16) float g_aedge[HH * 2];   // per-hyperedge attention scalar
__device__ __align__(16) float g_alpha[EE * 2];   // normalized attention [e][b]
__device__ __align__(16) float g_m[HH * 128];     // hyperedge messages [h][b*64+c] (2.56 MB)
__device__ int   g_bsum[64];                      // scan block sums

// ---------------------------------------------------------------------------
// K0: zero counters
// ---------------------------------------------------------------------------
__global__ void k_zero() {
    int i = blockIdx.x * blockDim.x + threadIdx.x;
    if (i < NN) { g_Dn[i] = 0; g_cursor[i] = 0; }
    if (i < HH) { g_De[i] = 0; }
}

// ---------------------------------------------------------------------------
// K1: GEMM  xw[r][d] = sum_c x[b][n][c] * W[c][d],  r = 2n+b
//     + per-row dots d1[r] = xw[r]·att1, d2[r] = xw[r]·att2
// Block: 256 threads handle 16 rows x 16 thread-groups of 4 channels.
// ---------------------------------------------------------------------------
__global__ void k_gemm(const float* __restrict__ x,
                       const float* __restrict__ W,
                       const float* __restrict__ att) {
    __shared__ float Ws[64 * 64];
    __shared__ float xs[16 * 68];   // stride 68 floats: 16B aligned, conflict-free

    int tid = threadIdx.x;
    // load weight (4096 floats = 1024 float4)
    for (int i = tid; i < 1024; i += 256)
        ((float4*)Ws)[i] = ((const float4*)W)[i];

    int rowblock = blockIdx.x * 16;
    {
        int rl = tid >> 4;          // 0..15 local row
        int cq = tid & 15;          // float4 index within row
        int r  = rowblock + rl;
        float4 v = make_float4(0.f, 0.f, 0.f, 0.f);
        if (r < RR) {
            int n = r >> 1, b = r & 1;
            v = ((const float4*)(x + (size_t)b * NN * 64 + (size_t)n * 64))[cq];
        }
        ((float4*)(xs + rl * 68))[cq] = v;
    }
    __syncthreads();

    int rl = tid >> 4;
    int r  = rowblock + rl;
    int d0 = (tid & 15) * 4;
    float4 acc = make_float4(0.f, 0.f, 0.f, 0.f);
#pragma unroll
    for (int c = 0; c < 64; c++) {
        float  xv = xs[rl * 68 + c];
        float4 w  = *(const float4*)(Ws + c * 64 + d0);
        acc.x += xv * w.x; acc.y += xv * w.y;
        acc.z += xv * w.z; acc.w += xv * w.w;
    }
    if (r < RR) {
        *(float4*)(g_xw + (size_t)r * 64 + d0) = acc;
        float p1 = acc.x * __ldg(att + d0)      + acc.y * __ldg(att + d0 + 1)
                 + acc.z * __ldg(att + d0 + 2)  + acc.w * __ldg(att + d0 + 3);
        float p2 = acc.x * __ldg(att + 64 + d0)     + acc.y * __ldg(att + 64 + d0 + 1)
                 + acc.z * __ldg(att + 64 + d0 + 2) + acc.w * __ldg(att + 64 + d0 + 3);
        // reduce across the 16 lanes owning this row (xor<16 stays in-half)
#pragma unroll
        for (int off = 8; off >= 1; off >>= 1) {
            p1 += __shfl_xor_sync(0xffffffffu, p1, off);
            p2 += __shfl_xor_sync(0xffffffffu, p2, off);
        }
        if ((tid & 15) == 0) { g_d1[r] = p1; g_d2[r] = p2; }
    }
}

// ---------------------------------------------------------------------------
// K2: degrees + hyperedge segment starts (hedge_idx is sorted)
// ---------------------------------------------------------------------------
__global__ void k_deg(const int* __restrict__ node_idx,
                      const int* __restrict__ hedge_idx) {
    int e = blockIdx.x * blockDim.x + threadIdx.x;
    if (e >= EE) return;
    atomicAdd(&g_Dn[node_idx[e]], 1);
    int h = hedge_idx[e];
    atomicAdd(&g_De[h], 1);
    if (e == 0 || hedge_idx[e - 1] != h) g_hstart[h] = e;
}

// ---------------------------------------------------------------------------
// K3a/b/c: exclusive scan of g_Dn -> g_nstart (two-level, 1024-wide blocks)
// ---------------------------------------------------------------------------
__global__ void k_scan1() {
    int i    = blockIdx.x * 1024 + threadIdx.x;
    int lane = threadIdx.x & 31, wid = threadIdx.x >> 5;
    int v = (i < NN) ? g_Dn[i] : 0;
    int x = v;
#pragma unroll
    for (int off = 1; off < 32; off <<= 1) {
        int y = __shfl_up_sync(0xffffffffu, x, off);
        if (lane >= off) x += y;
    }
    __shared__ int ws[32];
    if (lane == 31) ws[wid] = x;
    __syncthreads();
    if (wid == 0) {
        int s = ws[lane];
#pragma unroll
        for (int off = 1; off < 32; off <<= 1) {
            int y = __shfl_up_sync(0xffffffffu, s, off);
            if (lane >= off) s += y;
        }
        ws[lane] = s;
    }
    __syncthreads();
    int excl = x - v + ((wid > 0) ? ws[wid - 1] : 0);
    if (i < NN) g_nstart[i] = excl;
    if (threadIdx.x == 1023) g_bsum[blockIdx.x] = excl + v;
}

__global__ void k_scan2() {
    if (threadIdx.x == 0) {
        int s = 0;
        for (int k = 0; k < NBLK; k++) { int t = g_bsum[k]; g_bsum[k] = s; s += t; }
    }
}

__global__ void k_scan3() {
    int i = blockIdx.x * 1024 + threadIdx.x;
    if (i < NN) g_nstart[i] += g_bsum[blockIdx.x];
}

// ---------------------------------------------------------------------------
// K4: per-hyperedge attention scalar a_edge[h][b] = sum_{e in h} d2[2*node_e + b]
// (eliminates the [H,B,C] edge_sums tensor entirely)
// ---------------------------------------------------------------------------
__global__ void k_aedge(const int* __restrict__ node_idx) {
    int h = blockIdx.x;
    int cnt = g_De[h];
    if (cnt == 0) return;
    int start = g_hstart[h];
    int t = threadIdx.x;            // 128 threads = 4 warps
    float s0 = 0.f, s1 = 0.f;
    for (int i = t; i < cnt; i += 128) {
        int n = node_idx[start + i];
        float2 d = *(const float2*)(g_d2 + 2 * n);
        s0 += d.x; s1 += d.y;
    }
#pragma unroll
    for (int off = 16; off >= 1; off >>= 1) {
        s0 += __shfl_xor_sync(0xffffffffu, s0, off);
        s1 += __shfl_xor_sync(0xffffffffu, s1, off);
    }
    __shared__ float r0[4], r1[4];
    int lane = t & 31, wid = t >> 5;
    if (lane == 0) { r0[wid] = s0; r1[wid] = s1; }
    __syncthreads();
    if (t == 0) {
        float a0 = r0[0] + r0[1] + r0[2] + r0[3];
        float a1 = r1[0] + r1[1] + r1[2] + r1[3];
        g_aedge[2 * h]     = a0;
        g_aedge[2 * h + 1] = a1;
    }
}

// ---------------------------------------------------------------------------
// K5: counting-sort scatter: perm lists incidences grouped by node
// ---------------------------------------------------------------------------
__global__ void k_scatter(const int* __restrict__ node_idx) {
    int e = blockIdx.x * blockDim.x + threadIdx.x;
    if (e >= EE) return;
    int n = node_idx[e];
    int pos = g_nstart[n] + atomicAdd(&g_cursor[n], 1);
    g_perm[pos] = e;
}

// ---------------------------------------------------------------------------
// K6: segment softmax over node segments (warp per node)
// alpha_raw[e][b] = leakyrelu(d1[2n+b] + a_edge[2h+b], 0.2)
// ---------------------------------------------------------------------------
__global__ void k_softmax(const int* __restrict__ hedge_idx) {
    int gw   = (blockIdx.x * blockDim.x + threadIdx.x) >> 5;
    int lane = threadIdx.x & 31;
    if (gw >= NN) return;
    int n = gw, deg = g_Dn[n];
    if (deg == 0) return;
    int start = g_nstart[n];
    float base0 = g_d1[2 * n], base1 = g_d1[2 * n + 1];

    if (deg <= 32) {
        int e = 0;
        float v0 = -1e30f, v1 = -1e30f;
        if (lane < deg) {
            e = g_perm[start + lane];
            int h = hedge_idx[e];
            v0 = base0 + g_aedge[2 * h];
            v1 = base1 + g_aedge[2 * h + 1];
            v0 = (v0 >= 0.f) ? v0 : 0.2f * v0;
            v1 = (v1 >= 0.f) ? v1 : 0.2f * v1;
        }
        float m0 = v0, m1 = v1;
#pragma unroll
        for (int off = 16; off >= 1; off >>= 1) {
            m0 = fmaxf(m0, __shfl_xor_sync(0xffffffffu, m0, off));
            m1 = fmaxf(m1, __shfl_xor_sync(0xffffffffu, m1, off));
        }
        float e0 = (lane < deg) ? __expf(v0 - m0) : 0.f;
        float e1 = (lane < deg) ? __expf(v1 - m1) : 0.f;
        float s0 = e0, s1 = e1;
#pragma unroll
        for (int off = 16; off >= 1; off >>= 1) {
            s0 += __shfl_xor_sync(0xffffffffu, s0, off);
            s1 += __shfl_xor_sync(0xffffffffu, s1, off);
        }
        if (lane < deg) {
            g_alpha[2 * e]     = e0 / s0;
            g_alpha[2 * e + 1] = e1 / s1;
        }
    } else {
        // 3-pass recompute path for rare high-degree nodes
        float m0 = -1e30f, m1 = -1e30f;
        for (int j = lane; j < deg; j += 32) {
            int e = g_perm[start + j]; int h = hedge_idx[e];
            float v0 = base0 + g_aedge[2 * h];
            float v1 = base1 + g_aedge[2 * h + 1];
            v0 = (v0 >= 0.f) ? v0 : 0.2f * v0;
            v1 = (v1 >= 0.f) ? v1 : 0.2f * v1;
            m0 = fmaxf(m0, v0); m1 = fmaxf(m1, v1);
        }
#pragma unroll
        for (int off = 16; off >= 1; off >>= 1) {
            m0 = fmaxf(m0, __shfl_xor_sync(0xffffffffu, m0, off));
            m1 = fmaxf(m1, __shfl_xor_sync(0xffffffffu, m1, off));
        }
        float s0 = 0.f, s1 = 0.f;
        for (int j = lane; j < deg; j += 32) {
            int e = g_perm[start + j]; int h = hedge_idx[e];
            float v0 = base0 + g_aedge[2 * h];
            float v1 = base1 + g_aedge[2 * h + 1];
            v0 = (v0 >= 0.f) ? v0 : 0.2f * v0;
            v1 = (v1 >= 0.f) ? v1 : 0.2f * v1;
            s0 += __expf(v0 - m0); s1 += __expf(v1 - m1);
        }
#pragma unroll
        for (int off = 16; off >= 1; off >>= 1) {
            s0 += __shfl_xor_sync(0xffffffffu, s0, off);
            s1 += __shfl_xor_sync(0xffffffffu, s1, off);
        }
        for (int j = lane; j < deg; j += 32) {
            int e = g_perm[start + j]; int h = hedge_idx[e];
            float v0 = base0 + g_aedge[2 * h];
            float v1 = base1 + g_aedge[2 * h + 1];
            v0 = (v0 >= 0.f) ? v0 : 0.2f * v0;
            v1 = (v1 >= 0.f) ? v1 : 0.2f * v1;
            g_alpha[2 * e]     = __expf(v0 - m0) / s0;
            g_alpha[2 * e + 1] = __expf(v1 - m1) / s1;
        }
    }
}

// ---------------------------------------------------------------------------
// K7: pass1 nodes -> hyperedges: m[h][b*64+c] = (1/De) * sum alpha[e][b]*xw[node]
// block per hyperedge (hedge-sorted -> contiguous segment, no atomics)
// ---------------------------------------------------------------------------
__global__ void k_pass1(const int* __restrict__ node_idx) {
    int h = blockIdx.x;
    int cnt = g_De[h];
    if (cnt == 0) return;
    int start = g_hstart[h];
    int t = threadIdx.x;            // 128 = B*C, thread owns (b,c)
    int b = t >> 6;
    __shared__ int   sn[128];
    __shared__ float sa0[128], sa1[128];
    float acc = 0.f;
    for (int base = 0; base < cnt; base += 128) {
        int mlen = min(128, cnt - base);
        if (t < mlen) {
            int e = start + base + t;
            sn[t] = node_idx[e];
            float2 a = *(const float2*)(g_alpha + 2 * e);
            sa0[t] = a.x; sa1[t] = a.y;
        }
        __syncthreads();
        const float* sa = b ? sa1 : sa0;
#pragma unroll 4
        for (int i = 0; i < mlen; i++) {
            acc += sa[i] * g_xw[(size_t)sn[i] * 128 + t];
        }
        __syncthreads();
    }
    g_m[(size_t)h * 128 + t] = acc / (float)cnt;
}

// ---------------------------------------------------------------------------
// K8: pass2 hyperedges -> nodes: out[b][n][c] = Dn[n] * sum alpha[e][b]*m[h_e]
// warp per node on the node-sorted permutation (no atomics, m is L2-resident)
// ---------------------------------------------------------------------------
__global__ void k_pass2(const int* __restrict__ hedge_idx,
                        float* __restrict__ out) {
    int gw   = (blockIdx.x * blockDim.x + threadIdx.x) >> 5;
    int lane = threadIdx.x & 31;
    if (gw >= NN) return;
    int n = gw, deg = g_Dn[n];
    int start = g_nstart[n];
    float4 acc = make_float4(0.f, 0.f, 0.f, 0.f);

    for (int base = 0; base < deg; base += 32) {
        int cnt = min(32, deg - base);
        int h = 0; float2 a2 = make_float2(0.f, 0.f);
        if (lane < cnt) {
            int e = g_perm[start + base + lane];
            h  = hedge_idx[e];
            a2 = *(const float2*)(g_alpha + 2 * e);
        }
        for (int i = 0; i < cnt; i++) {
            int   hh = __shfl_sync(0xffffffffu, h,    i);
            float a0 = __shfl_sync(0xffffffffu, a2.x, i);
            float a1 = __shfl_sync(0xffffffffu, a2.y, i);
            float a  = (lane < 16) ? a0 : a1;
            float4 mv = *(const float4*)(g_m + (size_t)hh * 128 + lane * 4);
            acc.x += a * mv.x; acc.y += a * mv.y;
            acc.z += a * mv.z; acc.w += a * mv.w;
        }
    }
    float dn = (float)deg;          // Dn multiplies (NOT inverted in source)
    int b  = lane >> 4;
    int c0 = (lane & 15) * 4;
    float4 o = make_float4(dn * acc.x, dn * acc.y, dn * acc.z, dn * acc.w);
    *(float4*)(out + (size_t)b * NN * 64 + (size_t)n * 64 + c0) = o;
}

// ---------------------------------------------------------------------------
// Launch
// ---------------------------------------------------------------------------
extern "C" void kernel_launch(void* const* d_in, const int* in_sizes, int n_in,
                              void* d_out, int out_size) {
    const float* x         = (const float*)d_in[0];   // [B,N,C]
    const float* weight    = (const float*)d_in[1];   // [C,C]
    const float* att       = (const float*)d_in[2];   // [2C]
    const int*   node_idx  = (const int*)d_in[3];     // [E]
    const int*   hedge_idx = (const int*)d_in[4];     // [E] sorted
    float*       out       = (float*)d_out;           // [B,N,C]

    k_zero<<<(NN + 255) / 256, 256>>>();
    k_gemm<<<RR / 16, 256>>>(x, weight, att);
    k_deg<<<(EE + 255) / 256, 256>>>(node_idx, hedge_idx);
    k_scan1<<<NBLK, 1024>>>();
    k_scan2<<<1, 32>>>();
    k_scan3<<<NBLK, 1024>>>();
    k_aedge<<<HH, 128>>>(node_idx);
    k_scatter<<<(EE + 255) / 256, 256>>>(node_idx);
    k_softmax<<<(NN * 32 + 255) / 256, 256>>>(hedge_idx);
    k_pass1<<<HH, 128>>>(node_idx);
    k_pass2<<<(NN * 32 + 255) / 256, 256>>>(hedge_idx, out);
}